// round 4
// baseline (speedup 1.0000x reference)
#include <cuda_runtime.h>
#include <stdint.h>

#define N_NODES 100000
#define N_EDGES 6400000
#define C 32
#define BN_EPS 1e-5f

// ---------------- device scratch (static: no runtime allocation allowed) ----
__device__ int    g_is64;                   // 1 if edge_index is int64, else int32
__device__ int2   g_edge[N_EDGES];          // packed (src, dst) int32
__device__ int    g_deg[N_NODES];
__device__ float  g_dinv[N_NODES];
__device__ float4 g_hp[N_NODES * 8];        // h' = (x @ W) * dinv   (per layer)
__device__ float4 g_acc[N_NODES * 8];       // scatter accumulator
__device__ float  g_z[N_NODES * C];         // pre-BN activations
__device__ float  g_bn1[128];               // [0:32) sum [32:64) sumsq [64:96) a [96:128) c
__device__ float  g_bn2[128];
__device__ float  g_hp3[N_NODES];
__device__ float  g_acc3[N_NODES];

// ---------------- dtype detection -------------------------------------------
__global__ void k_detect(const unsigned long long* __restrict__ ei) {
    if (blockIdx.x == 0 && threadIdx.x == 0) {
        int is64 = 1;
        for (int i = 0; i < 64; i++) {
            if (ei[i] >= (unsigned long long)N_NODES) { is64 = 0; break; }
        }
        g_is64 = is64;
    }
}

// ---------------- zeroing ---------------------------------------------------
__global__ void k_zero_init() {
    int t = blockIdx.x * blockDim.x + threadIdx.x;
    int stride = gridDim.x * blockDim.x;
    float4 z4 = make_float4(0.f, 0.f, 0.f, 0.f);
    for (int i = t; i < N_NODES * 8; i += stride) g_acc[i] = z4;
    if (t < N_NODES) { g_deg[t] = 0; g_acc3[t] = 0.f; }
    if (t < 128) { g_bn1[t] = 0.f; g_bn2[t] = 0.f; }
}

__global__ void k_zero_acc() {
    int t = blockIdx.x * blockDim.x + threadIdx.x;
    int stride = gridDim.x * blockDim.x;
    float4 z4 = make_float4(0.f, 0.f, 0.f, 0.f);
    for (int i = t; i < N_NODES * 8; i += stride) g_acc[i] = z4;
}

// ---------------- prep: indices -> int2, degree count -----------------------
__global__ void k_prep(const void* __restrict__ eiraw) {
    const int is64 = g_is64;
    int t = blockIdx.x * blockDim.x + threadIdx.x;
    int stride = gridDim.x * blockDim.x;
    if (is64) {
        const long long* ei = (const long long*)eiraw;
        for (int i = t; i < N_EDGES; i += stride) {
            int s = (int)ei[i];
            int d = (int)ei[N_EDGES + i];
            if ((unsigned)s >= N_NODES) s = 0;   // defensive clamp
            if ((unsigned)d >= N_NODES) d = 0;
            g_edge[i] = make_int2(s, d);
            atomicAdd(&g_deg[d], 1);
        }
    } else {
        const int* ei = (const int*)eiraw;
        for (int i = t; i < N_EDGES; i += stride) {
            int s = ei[i];
            int d = ei[N_EDGES + i];
            if ((unsigned)s >= N_NODES) s = 0;
            if ((unsigned)d >= N_NODES) d = 0;
            g_edge[i] = make_int2(s, d);
            atomicAdd(&g_deg[d], 1);
        }
    }
}

__global__ void k_dinv() {
    int i = blockIdx.x * blockDim.x + threadIdx.x;
    if (i < N_NODES) g_dinv[i] = rsqrtf((float)(g_deg[i] + 1));  // +1 self-loop
}

// ---------------- layer 1: h' = (x @ W1) * dinv ------------------------------
__global__ void k_layer1(const float* __restrict__ x, const float* __restrict__ W1) {
    int i = blockIdx.x * blockDim.x + threadIdx.x;
    if (i >= N_NODES) return;
    float xv[5];
#pragma unroll
    for (int k = 0; k < 5; k++) xv[k] = x[i * 5 + k];
    float di = g_dinv[i];
#pragma unroll
    for (int cq = 0; cq < 8; cq++) {
        float o[4];
#pragma unroll
        for (int j = 0; j < 4; j++) {
            int c = cq * 4 + j;
            float a = 0.f;
#pragma unroll
            for (int k = 0; k < 5; k++) a += xv[k] * __ldg(&W1[k * 32 + c]);
            o[j] = a * di;
        }
        g_hp[i * 8 + cq] = make_float4(o[0], o[1], o[2], o[3]);
    }
}

// ---------------- 32-channel edge scatter: acc[dst] += h'[src] ---------------
// 8 lanes per edge, each lane moves one float4 via vector RED.
__global__ void k_scatter32() {
    int t = blockIdx.x * blockDim.x + threadIdx.x;
    int e = t >> 3;
    if (e >= N_EDGES) return;
    int q = t & 7;
    int2 ed = __ldg(&g_edge[e]);
    float4 v = __ldg(&g_hp[ed.x * 8 + q]);
    unsigned long long p = __cvta_generic_to_global(&g_acc[ed.y * 8 + q]);
    asm volatile("red.global.add.v4.f32 [%0], {%1,%2,%3,%4};"
                 :: "l"(p), "f"(v.x), "f"(v.y), "f"(v.z), "f"(v.w)
                 : "memory");
}

// ---------------- z = dinv*(acc + h') + b ; BN sum/sumsq ---------------------
// warp-per-node-stripe, lane == channel (coalesced 128B rows)
__global__ void k_zstats(const float* __restrict__ b, int which) {
    float* bn = which ? g_bn2 : g_bn1;
    const float* acc = reinterpret_cast<const float*>(g_acc);
    const float* hp  = reinterpret_cast<const float*>(g_hp);
    int gt = blockIdx.x * blockDim.x + threadIdx.x;
    int gw = gt >> 5;
    int lane = threadIdx.x & 31;
    int nw = (gridDim.x * blockDim.x) >> 5;
    float bl = b[lane];
    float s = 0.f, s2 = 0.f;
    for (int i = gw; i < N_NODES; i += nw) {
        float di = g_dinv[i];
        float v = di * (acc[i * 32 + lane] + hp[i * 32 + lane]) + bl;
        g_z[i * 32 + lane] = v;
        s += v;
        s2 += v * v;
    }
    atomicAdd(&bn[lane], s);
    atomicAdd(&bn[32 + lane], s2);
}

__global__ void k_bnparam(const float* __restrict__ gamma, const float* __restrict__ beta,
                          int which) {
    float* bn = which ? g_bn2 : g_bn1;
    int c = threadIdx.x;
    if (c < 32) {
        float inv_n = 1.0f / (float)N_NODES;
        float m = bn[c] * inv_n;
        float var = bn[32 + c] * inv_n - m * m;
        float a = gamma[c] * rsqrtf(var + BN_EPS);
        bn[64 + c] = a;
        bn[96 + c] = beta[c] - m * a;
    }
}

// ---------------- layer 2: h' = (relu(bn(z)) @ W2) * dinv --------------------
__global__ void k_layer2(const float* __restrict__ W2, int which) {
    __shared__ float sW[1024];
    __shared__ float sa[32], sc[32];
    const float* bn = which ? g_bn2 : g_bn1;
    for (int t = threadIdx.x; t < 1024; t += blockDim.x) sW[t] = W2[t];
    if (threadIdx.x < 32) {
        sa[threadIdx.x] = bn[64 + threadIdx.x];
        sc[threadIdx.x] = bn[96 + threadIdx.x];
    }
    __syncthreads();
    int i = blockIdx.x * blockDim.x + threadIdx.x;
    if (i >= N_NODES) return;
    float y[32];
#pragma unroll
    for (int c = 0; c < 32; c++)
        y[c] = fmaxf(g_z[i * 32 + c] * sa[c] + sc[c], 0.f);
    float o[32];
#pragma unroll
    for (int c2 = 0; c2 < 32; c2++) o[c2] = 0.f;
#pragma unroll
    for (int c = 0; c < 32; c++) {
        float yv = y[c];
#pragma unroll
        for (int c2 = 0; c2 < 32; c2++) o[c2] += yv * sW[c * 32 + c2];
    }
    float di = g_dinv[i];
#pragma unroll
    for (int cq = 0; cq < 8; cq++)
        g_hp[i * 8 + cq] = make_float4(o[cq * 4] * di, o[cq * 4 + 1] * di,
                                       o[cq * 4 + 2] * di, o[cq * 4 + 3] * di);
}

// ---------------- layer 3: hp3 = (relu(bn(z)) @ W3) * dinv -------------------
__global__ void k_layer3(const float* __restrict__ W3, int which) {
    const float* bn = which ? g_bn2 : g_bn1;
    int i = blockIdx.x * blockDim.x + threadIdx.x;
    if (i >= N_NODES) return;
    float a = 0.f;
#pragma unroll
    for (int c = 0; c < 32; c++) {
        float v = g_z[i * 32 + c] * bn[64 + c] + bn[96 + c];
        v = fmaxf(v, 0.f);
        a += v * __ldg(&W3[c]);
    }
    g_hp3[i] = a * g_dinv[i];
}

// ---------------- 1-channel edge scatter -------------------------------------
__global__ void k_scatter1() {
    int t = blockIdx.x * blockDim.x + threadIdx.x;
    int stride = gridDim.x * blockDim.x;
    for (int e = t; e < N_EDGES; e += stride) {
        int2 ed = __ldg(&g_edge[e]);
        atomicAdd(&g_acc3[ed.y], g_hp3[ed.x]);
    }
}

// ---------------- final output -----------------------------------------------
__global__ void k_final(const float* __restrict__ b3, float* __restrict__ out) {
    int i = blockIdx.x * blockDim.x + threadIdx.x;
    if (i < N_NODES)
        out[i] = g_dinv[i] * (g_acc3[i] + g_hp3[i]) + b3[0];
}

// =============================================================================
extern "C" void kernel_launch(void* const* d_in, const int* in_sizes, int n_in,
                              void* d_out, int out_size) {
    const float* x      = (const float*)d_in[0];
    const void*  ei     = d_in[1];
    const float* W1     = (const float*)d_in[2];
    const float* b1     = (const float*)d_in[3];
    const float* gamma1 = (const float*)d_in[4];
    const float* beta1  = (const float*)d_in[5];
    const float* W2     = (const float*)d_in[6];
    const float* b2     = (const float*)d_in[7];
    const float* gamma2 = (const float*)d_in[8];
    const float* beta2  = (const float*)d_in[9];
    const float* W3     = (const float*)d_in[10];
    const float* b3     = (const float*)d_in[11];
    float* out = (float*)d_out;

    const int TB = 256;
    const int nodeBlocks = (N_NODES + TB - 1) / TB;          // 391
    const int accBlocks  = (N_NODES * 8 + TB - 1) / TB;      // 3125
    const int edgeBlocks = (N_EDGES + TB - 1) / TB;          // 25000
    const int scatBlocks = (N_EDGES * 8 + TB - 1) / TB;      // 200000

    k_detect<<<1, 32>>>((const unsigned long long*)ei);
    k_zero_init<<<accBlocks + 512, TB>>>();
    k_prep<<<edgeBlocks, TB>>>(ei);
    k_dinv<<<nodeBlocks, TB>>>();

    // ---- layer 1
    k_layer1<<<nodeBlocks, TB>>>(x, W1);
    k_scatter32<<<scatBlocks, TB>>>();
    k_zstats<<<2048, TB>>>(b1, 0);
    k_bnparam<<<1, 32>>>(gamma1, beta1, 0);

    // ---- layer 2
    k_zero_acc<<<accBlocks, TB>>>();
    k_layer2<<<nodeBlocks, TB>>>(W2, 0);
    k_scatter32<<<scatBlocks, TB>>>();
    k_zstats<<<2048, TB>>>(b2, 1);
    k_bnparam<<<1, 32>>>(gamma2, beta2, 1);

    // ---- layer 3
    k_layer3<<<nodeBlocks, TB>>>(W3, 1);
    k_scatter1<<<edgeBlocks, TB>>>();
    k_final<<<nodeBlocks, TB>>>(b3, out);
}

// round 5
// speedup vs baseline: 1.0779x; 1.0779x over previous
#include <cuda_runtime.h>
#include <stdint.h>

#define N_NODES 100000
#define N_EDGES 6400000
#define C 32
#define BN_EPS 1e-5f

// ---------------- device scratch (static) ------------------------------------
__device__ int    g_is64;                 // 1 if edge_index is int64, else int32
__device__ int    g_deg[N_NODES];
__device__ int    g_off[N_NODES + 1];     // CSR row offsets (by dst)
__device__ int    g_cur[N_NODES];         // fill cursors
__device__ int    g_csr[N_EDGES];         // src indices grouped by dst
__device__ float  g_dinv[N_NODES];
__device__ float4 g_hp[N_NODES * 8];      // h' = (feat @ W) * dinv (per layer)
__device__ float  g_z[N_NODES * C];       // pre-BN activations
__device__ float  g_bn1[128];             // [0:32) sum [32:64) sumsq [64:96) a [96:128) c
__device__ float  g_bn2[128];
__device__ float  g_hp3[N_NODES];

// ---------------- dtype detection --------------------------------------------
__global__ void k_detect(const unsigned long long* __restrict__ ei) {
    if (threadIdx.x == 0) {
        int is64 = 1;
        for (int i = 0; i < 64; i++)
            if (ei[i] >= (unsigned long long)N_NODES) { is64 = 0; break; }
        g_is64 = is64;
    }
}

// ---------------- zero small state --------------------------------------------
__global__ void k_zero() {
    int t = blockIdx.x * blockDim.x + threadIdx.x;
    int stride = gridDim.x * blockDim.x;
    for (int i = t; i < N_NODES; i += stride) g_deg[i] = 0;
    if (t < 128) { g_bn1[t] = 0.f; g_bn2[t] = 0.f; }
}

// ---------------- degree histogram (reads dst half only) ----------------------
__global__ void k_deg(const void* __restrict__ eiraw) {
    const int is64 = g_is64;
    int t = blockIdx.x * blockDim.x + threadIdx.x;
    int stride = gridDim.x * blockDim.x;
    if (is64) {
        const long long* ei = (const long long*)eiraw;
        for (int i = t; i < N_EDGES; i += stride) {
            int d = (int)ei[N_EDGES + i];
            if ((unsigned)d >= N_NODES) d = 0;
            atomicAdd(&g_deg[d], 1);
        }
    } else {
        const int* ei = (const int*)eiraw;
        for (int i = t; i < N_EDGES; i += stride) {
            int d = ei[N_EDGES + i];
            if ((unsigned)d >= N_NODES) d = 0;
            atomicAdd(&g_deg[d], 1);
        }
    }
}

// ---------------- single-block prefix scan -> offsets, cursors, dinv ----------
__global__ void k_scan() {
    __shared__ int ssum[1024];
    const int t = threadIdx.x;
    const int PER = (N_NODES + 1023) / 1024;   // 98
    int base = t * PER;
    int lim = base + PER; if (lim > N_NODES) lim = N_NODES;
    int s = 0;
    for (int i = base; i < lim; i++) s += g_deg[i];
    ssum[t] = s;
    __syncthreads();
    for (int off = 1; off < 1024; off <<= 1) {
        int v = (t >= off) ? ssum[t - off] : 0;
        __syncthreads();
        ssum[t] += v;
        __syncthreads();
    }
    int run = (t > 0) ? ssum[t - 1] : 0;
    for (int i = base; i < lim; i++) {
        g_off[i] = run;
        g_cur[i] = run;
        g_dinv[i] = rsqrtf((float)(g_deg[i] + 1));   // +1 self-loop
        run += g_deg[i];
    }
    if (t == 1023) g_off[N_NODES] = run;
}

// ---------------- counting-sort fill: csr[cur[dst]++] = src -------------------
__global__ void k_fill(const void* __restrict__ eiraw) {
    const int is64 = g_is64;
    int t = blockIdx.x * blockDim.x + threadIdx.x;
    int stride = gridDim.x * blockDim.x;
    if (is64) {
        const long long* ei = (const long long*)eiraw;
        for (int i = t; i < N_EDGES; i += stride) {
            int s = (int)ei[i];
            int d = (int)ei[N_EDGES + i];
            if ((unsigned)s >= N_NODES) s = 0;
            if ((unsigned)d >= N_NODES) d = 0;
            g_csr[atomicAdd(&g_cur[d], 1)] = s;
        }
    } else {
        const int* ei = (const int*)eiraw;
        for (int i = t; i < N_EDGES; i += stride) {
            int s = ei[i];
            int d = ei[N_EDGES + i];
            if ((unsigned)s >= N_NODES) s = 0;
            if ((unsigned)d >= N_NODES) d = 0;
            g_csr[atomicAdd(&g_cur[d], 1)] = s;
        }
    }
}

// ---------------- layer 1: h' = (x @ W1) * dinv --------------------------------
__global__ void k_layer1(const float* __restrict__ x, const float* __restrict__ W1) {
    int i = blockIdx.x * blockDim.x + threadIdx.x;
    if (i >= N_NODES) return;
    float xv[5];
#pragma unroll
    for (int k = 0; k < 5; k++) xv[k] = x[i * 5 + k];
    float di = g_dinv[i];
#pragma unroll
    for (int cq = 0; cq < 8; cq++) {
        float o[4];
#pragma unroll
        for (int j = 0; j < 4; j++) {
            int c = cq * 4 + j;
            float a = 0.f;
#pragma unroll
            for (int k = 0; k < 5; k++) a += xv[k] * __ldg(&W1[k * 32 + c]);
            o[j] = a * di;
        }
        g_hp[i * 8 + cq] = make_float4(o[0], o[1], o[2], o[3]);
    }
}

// ---------------- fused aggregate + z + BN stats -------------------------------
// warp per node, lane = channel. Edges staged 32-at-a-time: coalesced index
// load then shfl broadcast; each edge = one coalesced 128B row gather.
__global__ void k_agg32(const float* __restrict__ b, int which) {
    __shared__ float sb[64];
    float* bn = which ? g_bn2 : g_bn1;
    const float* hp = reinterpret_cast<const float*>(g_hp);
    const int lane = threadIdx.x & 31;
    const int wid = threadIdx.x >> 5;
    const int nwpb = blockDim.x >> 5;
    if (threadIdx.x < 64) sb[threadIdx.x] = 0.f;
    __syncthreads();

    int node = blockIdx.x * nwpb + wid;
    float s = 0.f, s2 = 0.f;
    if (node < N_NODES) {
        int start = g_off[node];
        int end = g_off[node + 1];
        float acc = hp[node * 32 + lane];            // self-loop
        for (int p = start; p < end; p += 32) {
            int m = end - p; if (m > 32) m = 32;
            int sidx = (lane < m) ? __ldg(&g_csr[p + lane]) : 0;
            int j = 0;
            for (; j + 4 <= m; j += 4) {
                int s0 = __shfl_sync(0xffffffffu, sidx, j);
                int s1 = __shfl_sync(0xffffffffu, sidx, j + 1);
                int s2i = __shfl_sync(0xffffffffu, sidx, j + 2);
                int s3 = __shfl_sync(0xffffffffu, sidx, j + 3);
                float v0 = __ldg(&hp[s0 * 32 + lane]);
                float v1 = __ldg(&hp[s1 * 32 + lane]);
                float v2 = __ldg(&hp[s2i * 32 + lane]);
                float v3 = __ldg(&hp[s3 * 32 + lane]);
                acc += v0 + v1 + v2 + v3;
            }
            for (; j < m; j++) {
                int sj = __shfl_sync(0xffffffffu, sidx, j);
                acc += __ldg(&hp[sj * 32 + lane]);
            }
        }
        float v = g_dinv[node] * acc + b[lane];
        g_z[node * 32 + lane] = v;
        s = v; s2 = v * v;
    }
    atomicAdd(&sb[lane], s);
    atomicAdd(&sb[32 + lane], s2);
    __syncthreads();
    if (threadIdx.x < 64) atomicAdd(&bn[threadIdx.x], sb[threadIdx.x]);
}

__global__ void k_bnparam(const float* __restrict__ gamma, const float* __restrict__ beta,
                          int which) {
    float* bn = which ? g_bn2 : g_bn1;
    int c = threadIdx.x;
    if (c < 32) {
        float inv_n = 1.0f / (float)N_NODES;
        float m = bn[c] * inv_n;
        float var = bn[32 + c] * inv_n - m * m;
        float a = gamma[c] * rsqrtf(var + BN_EPS);
        bn[64 + c] = a;
        bn[96 + c] = beta[c] - m * a;
    }
}

// ---------------- layer 2: h' = (relu(bn(z)) @ W2) * dinv ----------------------
__global__ void k_layer2(const float* __restrict__ W2, int which) {
    __shared__ float sW[1024];
    __shared__ float sa[32], sc[32];
    const float* bn = which ? g_bn2 : g_bn1;
    for (int t = threadIdx.x; t < 1024; t += blockDim.x) sW[t] = W2[t];
    if (threadIdx.x < 32) {
        sa[threadIdx.x] = bn[64 + threadIdx.x];
        sc[threadIdx.x] = bn[96 + threadIdx.x];
    }
    __syncthreads();
    int i = blockIdx.x * blockDim.x + threadIdx.x;
    if (i >= N_NODES) return;
    float y[32];
#pragma unroll
    for (int c = 0; c < 32; c++)
        y[c] = fmaxf(g_z[i * 32 + c] * sa[c] + sc[c], 0.f);
    float o[32];
#pragma unroll
    for (int c2 = 0; c2 < 32; c2++) o[c2] = 0.f;
#pragma unroll
    for (int c = 0; c < 32; c++) {
        float yv = y[c];
#pragma unroll
        for (int c2 = 0; c2 < 32; c2++) o[c2] += yv * sW[c * 32 + c2];
    }
    float di = g_dinv[i];
#pragma unroll
    for (int cq = 0; cq < 8; cq++)
        g_hp[i * 8 + cq] = make_float4(o[cq * 4] * di, o[cq * 4 + 1] * di,
                                       o[cq * 4 + 2] * di, o[cq * 4 + 3] * di);
}

// ---------------- layer 3: hp3 = (relu(bn(z)) @ W3) * dinv ---------------------
__global__ void k_layer3(const float* __restrict__ W3, int which) {
    const float* bn = which ? g_bn2 : g_bn1;
    int i = blockIdx.x * blockDim.x + threadIdx.x;
    if (i >= N_NODES) return;
    float a = 0.f;
#pragma unroll
    for (int c = 0; c < 32; c++) {
        float v = g_z[i * 32 + c] * bn[64 + c] + bn[96 + c];
        v = fmaxf(v, 0.f);
        a += v * __ldg(&W3[c]);
    }
    g_hp3[i] = a * g_dinv[i];
}

// ---------------- final: out = dinv*(sum_in hp3 + hp3) + b3 --------------------
// warp per node, lane-parallel edges + shfl reduce.
__global__ void k_agg1(const float* __restrict__ b3, float* __restrict__ out) {
    const int lane = threadIdx.x & 31;
    const int wid = threadIdx.x >> 5;
    const int nwpb = blockDim.x >> 5;
    int node = blockIdx.x * nwpb + wid;
    if (node >= N_NODES) return;
    int start = g_off[node];
    int end = g_off[node + 1];
    float a = 0.f;
    for (int p = start + lane; p < end; p += 32)
        a += __ldg(&g_hp3[__ldg(&g_csr[p])]);
#pragma unroll
    for (int o = 16; o; o >>= 1) a += __shfl_xor_sync(0xffffffffu, a, o);
    if (lane == 0)
        out[node] = g_dinv[node] * (a + g_hp3[node]) + b3[0];
}

// =============================================================================
extern "C" void kernel_launch(void* const* d_in, const int* in_sizes, int n_in,
                              void* d_out, int out_size) {
    const float* x      = (const float*)d_in[0];
    const void*  ei     = d_in[1];
    const float* W1     = (const float*)d_in[2];
    const float* b1     = (const float*)d_in[3];
    const float* gamma1 = (const float*)d_in[4];
    const float* beta1  = (const float*)d_in[5];
    const float* W2     = (const float*)d_in[6];
    const float* b2     = (const float*)d_in[7];
    const float* gamma2 = (const float*)d_in[8];
    const float* beta2  = (const float*)d_in[9];
    const float* W3     = (const float*)d_in[10];
    const float* b3     = (const float*)d_in[11];
    float* out = (float*)d_out;

    const int TB = 256;
    const int nodeBlocks = (N_NODES + TB - 1) / TB;          // 391
    const int edgeBlocks = (N_EDGES + TB - 1) / TB;          // 25000
    const int warpBlocks = (N_NODES * 32 + TB - 1) / TB;     // 12500 (warp/node)

    k_detect<<<1, 32>>>((const unsigned long long*)ei);
    k_zero<<<nodeBlocks, TB>>>();
    k_deg<<<edgeBlocks, TB>>>(ei);
    k_scan<<<1, 1024>>>();
    k_fill<<<edgeBlocks, TB>>>(ei);

    // ---- layer 1
    k_layer1<<<nodeBlocks, TB>>>(x, W1);
    k_agg32<<<warpBlocks, TB>>>(b1, 0);
    k_bnparam<<<1, 32>>>(gamma1, beta1, 0);

    // ---- layer 2
    k_layer2<<<nodeBlocks, TB>>>(W2, 0);
    k_agg32<<<warpBlocks, TB>>>(b2, 1);
    k_bnparam<<<1, 32>>>(gamma2, beta2, 1);

    // ---- layer 3
    k_layer3<<<nodeBlocks, TB>>>(W3, 1);
    k_agg1<<<warpBlocks, TB>>>(b3, out);
}

// round 6
// speedup vs baseline: 1.6888x; 1.5667x over previous
#include <cuda_runtime.h>
#include <stdint.h>

#define N_NODES 100000
#define N_EDGES 6400000
#define C 32
#define BN_EPS 1e-5f

#define SCAN_TB 512
#define SCAN_NB 196   // 196 * 512 = 100352 >= N_NODES

// ---------------- device scratch (static) ------------------------------------
__device__ int    g_is64;                 // 1 if edge_index is int64, else int32
__device__ int    g_deg[N_NODES];
__device__ int    g_bsum[SCAN_NB];        // block sums for multi-block scan
__device__ int    g_off[N_NODES + 1];     // CSR row offsets (by dst)
__device__ int    g_cur[N_NODES];         // fill cursors
__device__ int    g_csr[N_EDGES];         // src indices grouped by dst
__device__ float  g_dinv[N_NODES];
__device__ float4 g_hp[N_NODES * 8];      // h' = (feat @ W) * dinv (per layer)
__device__ float  g_z[N_NODES * C];       // pre-BN activations
__device__ float  g_bn1[128];             // [0:32) sum [32:64) sumsq [64:96) a [96:128) c
__device__ float  g_bn2[128];
__device__ float  g_hp3[N_NODES];

// ---------------- dtype detection --------------------------------------------
__global__ void k_detect(const unsigned long long* __restrict__ ei) {
    if (threadIdx.x == 0) {
        int is64 = 1;
        for (int i = 0; i < 64; i++)
            if (ei[i] >= (unsigned long long)N_NODES) { is64 = 0; break; }
        g_is64 = is64;
    }
}

// ---------------- zero small state --------------------------------------------
__global__ void k_zero() {
    int t = blockIdx.x * blockDim.x + threadIdx.x;
    int stride = gridDim.x * blockDim.x;
    for (int i = t; i < N_NODES; i += stride) g_deg[i] = 0;
    if (t < 128) { g_bn1[t] = 0.f; g_bn2[t] = 0.f; }
}

// ---------------- degree histogram (reads dst half only) ----------------------
__global__ void k_deg(const void* __restrict__ eiraw) {
    const int is64 = g_is64;
    int t = blockIdx.x * blockDim.x + threadIdx.x;
    int stride = gridDim.x * blockDim.x;
    if (is64) {
        const long long* ei = (const long long*)eiraw;
        for (int i = t; i < N_EDGES; i += stride) {
            int d = (int)ei[N_EDGES + i];
            if ((unsigned)d >= N_NODES) d = 0;
            atomicAdd(&g_deg[d], 1);
        }
    } else {
        const int* ei = (const int*)eiraw;
        for (int i = t; i < N_EDGES; i += stride) {
            int d = ei[N_EDGES + i];
            if ((unsigned)d >= N_NODES) d = 0;
            atomicAdd(&g_deg[d], 1);
        }
    }
}

// ---------------- phase A: per-block degree sums -------------------------------
__global__ void k_scanA() {
    __shared__ int s[SCAN_TB];
    int t = threadIdx.x;
    int i = blockIdx.x * SCAN_TB + t;
    s[t] = (i < N_NODES) ? g_deg[i] : 0;
    __syncthreads();
    for (int o = SCAN_TB / 2; o > 0; o >>= 1) {
        if (t < o) s[t] += s[t + o];
        __syncthreads();
    }
    if (t == 0) g_bsum[blockIdx.x] = s[0];
}

// ---------------- phase B: scan block sums (one small block) -------------------
__global__ void k_scanB() {
    __shared__ int s[256];
    int t = threadIdx.x;
    int v = (t < SCAN_NB) ? g_bsum[t] : 0;
    s[t] = v;
    __syncthreads();
    for (int o = 1; o < 256; o <<= 1) {
        int u = (t >= o) ? s[t - o] : 0;
        __syncthreads();
        s[t] += u;
        __syncthreads();
    }
    if (t < SCAN_NB) g_bsum[t] = s[t] - v;          // exclusive prefix
    if (t == SCAN_NB - 1) g_off[N_NODES] = s[t];    // total edge count
}

// ---------------- phase C: intra-block scan + write off/cur/dinv ---------------
__global__ void k_scanC() {
    __shared__ int s[SCAN_TB];
    int t = threadIdx.x;
    int i = blockIdx.x * SCAN_TB + t;
    int d = (i < N_NODES) ? g_deg[i] : 0;
    s[t] = d;
    __syncthreads();
    for (int o = 1; o < SCAN_TB; o <<= 1) {
        int u = (t >= o) ? s[t - o] : 0;
        __syncthreads();
        s[t] += u;
        __syncthreads();
    }
    if (i < N_NODES) {
        int off = g_bsum[blockIdx.x] + s[t] - d;    // exclusive
        g_off[i] = off;
        g_cur[i] = off;
        g_dinv[i] = rsqrtf((float)(d + 1));          // +1 self-loop
    }
}

// ---------------- counting-sort fill: csr[cur[dst]++] = src --------------------
__global__ void k_fill(const void* __restrict__ eiraw) {
    const int is64 = g_is64;
    int t = blockIdx.x * blockDim.x + threadIdx.x;
    int stride = gridDim.x * blockDim.x;
    if (is64) {
        const long long* ei = (const long long*)eiraw;
        for (int i = t; i < N_EDGES; i += stride) {
            int s = (int)ei[i];
            int d = (int)ei[N_EDGES + i];
            if ((unsigned)s >= N_NODES) s = 0;
            if ((unsigned)d >= N_NODES) d = 0;
            g_csr[atomicAdd(&g_cur[d], 1)] = s;
        }
    } else {
        const int* ei = (const int*)eiraw;
        for (int i = t; i < N_EDGES; i += stride) {
            int s = ei[i];
            int d = ei[N_EDGES + i];
            if ((unsigned)s >= N_NODES) s = 0;
            if ((unsigned)d >= N_NODES) d = 0;
            g_csr[atomicAdd(&g_cur[d], 1)] = s;
        }
    }
}

// ---------------- layer 1: h' = (x @ W1) * dinv --------------------------------
__global__ void k_layer1(const float* __restrict__ x, const float* __restrict__ W1) {
    int i = blockIdx.x * blockDim.x + threadIdx.x;
    if (i >= N_NODES) return;
    float xv[5];
#pragma unroll
    for (int k = 0; k < 5; k++) xv[k] = x[i * 5 + k];
    float di = g_dinv[i];
#pragma unroll
    for (int cq = 0; cq < 8; cq++) {
        float o[4];
#pragma unroll
        for (int j = 0; j < 4; j++) {
            int c = cq * 4 + j;
            float a = 0.f;
#pragma unroll
            for (int k = 0; k < 5; k++) a += xv[k] * __ldg(&W1[k * 32 + c]);
            o[j] = a * di;
        }
        g_hp[i * 8 + cq] = make_float4(o[0], o[1], o[2], o[3]);
    }
}

// ---------------- fused aggregate + z + BN stats -------------------------------
// warp per node, lane = channel. Edges staged 32-at-a-time: coalesced index
// load then shfl broadcast; each edge = one coalesced 128B row gather.
__global__ void k_agg32(const float* __restrict__ b, int which) {
    __shared__ float sb[64];
    float* bn = which ? g_bn2 : g_bn1;
    const float* hp = reinterpret_cast<const float*>(g_hp);
    const int lane = threadIdx.x & 31;
    const int wid = threadIdx.x >> 5;
    const int nwpb = blockDim.x >> 5;
    if (threadIdx.x < 64) sb[threadIdx.x] = 0.f;
    __syncthreads();

    int node = blockIdx.x * nwpb + wid;
    float s = 0.f, s2 = 0.f;
    if (node < N_NODES) {
        int start = g_off[node];
        int end = g_off[node + 1];
        float acc = hp[node * 32 + lane];            // self-loop
        for (int p = start; p < end; p += 32) {
            int m = end - p; if (m > 32) m = 32;
            int sidx = (lane < m) ? __ldg(&g_csr[p + lane]) : 0;
            int j = 0;
            for (; j + 4 <= m; j += 4) {
                int s0 = __shfl_sync(0xffffffffu, sidx, j);
                int s1 = __shfl_sync(0xffffffffu, sidx, j + 1);
                int s2i = __shfl_sync(0xffffffffu, sidx, j + 2);
                int s3 = __shfl_sync(0xffffffffu, sidx, j + 3);
                float v0 = __ldg(&hp[s0 * 32 + lane]);
                float v1 = __ldg(&hp[s1 * 32 + lane]);
                float v2 = __ldg(&hp[s2i * 32 + lane]);
                float v3 = __ldg(&hp[s3 * 32 + lane]);
                acc += v0 + v1 + v2 + v3;
            }
            for (; j < m; j++) {
                int sj = __shfl_sync(0xffffffffu, sidx, j);
                acc += __ldg(&hp[sj * 32 + lane]);
            }
        }
        float v = g_dinv[node] * acc + b[lane];
        g_z[node * 32 + lane] = v;
        s = v; s2 = v * v;
    }
    atomicAdd(&sb[lane], s);
    atomicAdd(&sb[32 + lane], s2);
    __syncthreads();
    if (threadIdx.x < 64) atomicAdd(&bn[threadIdx.x], sb[threadIdx.x]);
}

__global__ void k_bnparam(const float* __restrict__ gamma, const float* __restrict__ beta,
                          int which) {
    float* bn = which ? g_bn2 : g_bn1;
    int c = threadIdx.x;
    if (c < 32) {
        float inv_n = 1.0f / (float)N_NODES;
        float m = bn[c] * inv_n;
        float var = bn[32 + c] * inv_n - m * m;
        float a = gamma[c] * rsqrtf(var + BN_EPS);
        bn[64 + c] = a;
        bn[96 + c] = beta[c] - m * a;
    }
}

// ---------------- layer 2: h' = (relu(bn(z)) @ W2) * dinv ----------------------
__global__ void k_layer2(const float* __restrict__ W2, int which) {
    __shared__ float sW[1024];
    __shared__ float sa[32], sc[32];
    const float* bn = which ? g_bn2 : g_bn1;
    for (int t = threadIdx.x; t < 1024; t += blockDim.x) sW[t] = W2[t];
    if (threadIdx.x < 32) {
        sa[threadIdx.x] = bn[64 + threadIdx.x];
        sc[threadIdx.x] = bn[96 + threadIdx.x];
    }
    __syncthreads();
    int i = blockIdx.x * blockDim.x + threadIdx.x;
    if (i >= N_NODES) return;
    float y[32];
#pragma unroll
    for (int c = 0; c < 32; c++)
        y[c] = fmaxf(g_z[i * 32 + c] * sa[c] + sc[c], 0.f);
    float o[32];
#pragma unroll
    for (int c2 = 0; c2 < 32; c2++) o[c2] = 0.f;
#pragma unroll
    for (int c = 0; c < 32; c++) {
        float yv = y[c];
#pragma unroll
        for (int c2 = 0; c2 < 32; c2++) o[c2] += yv * sW[c * 32 + c2];
    }
    float di = g_dinv[i];
#pragma unroll
    for (int cq = 0; cq < 8; cq++)
        g_hp[i * 8 + cq] = make_float4(o[cq * 4] * di, o[cq * 4 + 1] * di,
                                       o[cq * 4 + 2] * di, o[cq * 4 + 3] * di);
}

// ---------------- layer 3: hp3 = (relu(bn(z)) @ W3) * dinv ---------------------
__global__ void k_layer3(const float* __restrict__ W3, int which) {
    const float* bn = which ? g_bn2 : g_bn1;
    int i = blockIdx.x * blockDim.x + threadIdx.x;
    if (i >= N_NODES) return;
    float a = 0.f;
#pragma unroll
    for (int c = 0; c < 32; c++) {
        float v = g_z[i * 32 + c] * bn[64 + c] + bn[96 + c];
        v = fmaxf(v, 0.f);
        a += v * __ldg(&W3[c]);
    }
    g_hp3[i] = a * g_dinv[i];
}

// ---------------- final: out = dinv*(sum_in hp3 + hp3) + b3 --------------------
__global__ void k_agg1(const float* __restrict__ b3, float* __restrict__ out) {
    const int lane = threadIdx.x & 31;
    const int wid = threadIdx.x >> 5;
    const int nwpb = blockDim.x >> 5;
    int node = blockIdx.x * nwpb + wid;
    if (node >= N_NODES) return;
    int start = g_off[node];
    int end = g_off[node + 1];
    float a = 0.f;
    for (int p = start + lane; p < end; p += 32)
        a += __ldg(&g_hp3[__ldg(&g_csr[p])]);
#pragma unroll
    for (int o = 16; o; o >>= 1) a += __shfl_xor_sync(0xffffffffu, a, o);
    if (lane == 0)
        out[node] = g_dinv[node] * (a + g_hp3[node]) + b3[0];
}

// =============================================================================
extern "C" void kernel_launch(void* const* d_in, const int* in_sizes, int n_in,
                              void* d_out, int out_size) {
    const float* x      = (const float*)d_in[0];
    const void*  ei     = d_in[1];
    const float* W1     = (const float*)d_in[2];
    const float* b1     = (const float*)d_in[3];
    const float* gamma1 = (const float*)d_in[4];
    const float* beta1  = (const float*)d_in[5];
    const float* W2     = (const float*)d_in[6];
    const float* b2     = (const float*)d_in[7];
    const float* gamma2 = (const float*)d_in[8];
    const float* beta2  = (const float*)d_in[9];
    const float* W3     = (const float*)d_in[10];
    const float* b3     = (const float*)d_in[11];
    float* out = (float*)d_out;

    const int TB = 256;
    const int nodeBlocks = (N_NODES + TB - 1) / TB;          // 391
    const int edgeBlocks = (N_EDGES + TB - 1) / TB;          // 25000
    const int warpBlocks = (N_NODES * 32 + TB - 1) / TB;     // 12500 (warp/node)

    k_detect<<<1, 32>>>((const unsigned long long*)ei);
    k_zero<<<nodeBlocks, TB>>>();
    k_deg<<<edgeBlocks, TB>>>(ei);
    k_scanA<<<SCAN_NB, SCAN_TB>>>();
    k_scanB<<<1, 256>>>();
    k_scanC<<<SCAN_NB, SCAN_TB>>>();
    k_fill<<<edgeBlocks, TB>>>(ei);

    // ---- layer 1
    k_layer1<<<nodeBlocks, TB>>>(x, W1);
    k_agg32<<<warpBlocks, TB>>>(b1, 0);
    k_bnparam<<<1, 32>>>(gamma1, beta1, 0);

    // ---- layer 2
    k_layer2<<<nodeBlocks, TB>>>(W2, 0);
    k_agg32<<<warpBlocks, TB>>>(b2, 1);
    k_bnparam<<<1, 32>>>(gamma2, beta2, 1);

    // ---- layer 3
    k_layer3<<<nodeBlocks, TB>>>(W3, 1);
    k_agg1<<<warpBlocks, TB>>>(b3, out);
}